// round 1
// baseline (speedup 1.0000x reference)
#include <cuda_runtime.h>

#define NS 13824            // D*H*W = 24*24*24
#define NB 2                // batch
#define NC 64               // channels
#define NVOX (NB * NS)      // 27648 voxels total

// Scratch: q (pre-scaled by hd^-0.5), k, v in voxel-major layout [n][c]
__device__ float g_q[NVOX * NC];
__device__ float g_k[NVOX * NC];
__device__ float g_v[NVOX * NC];

// ---------------------------------------------------------------------------
// Kernel 1: QKV projection. One block = 64 consecutive voxels of one batch.
// q/k/v[n][c] = bias[c] + sum_j W[c][j] * x[b][j][s]   (q additionally * 0.25)
// ---------------------------------------------------------------------------
__global__ __launch_bounds__(256) void k_proj(
    const float* __restrict__ x,
    const float* __restrict__ Wq, const float* __restrict__ bq,
    const float* __restrict__ Wk, const float* __restrict__ bk,
    const float* __restrict__ Wv, const float* __restrict__ bv)
{
    __shared__ float WT[64 * 66];   // W transposed: WT[j*66 + c] = W[c][j]
    __shared__ float Xs[64 * 64];   // Xs[j*64 + t] = x[b][j][s0+t]
    __shared__ float bs[64];

    const int tid  = threadIdx.x;
    const int tile = blockIdx.x;              // 0..431
    const int bb   = tile / (NS / 64);        // batch
    const int s0   = (tile % (NS / 64)) * 64; // spatial base

    const float* xb = x + (long)bb * NC * NS + s0;

    // Load x tile, coalesced
#pragma unroll
    for (int k = 0; k < 16; k++) {
        int idx = tid + k * 256;
        int c = idx >> 6, u = idx & 63;
        Xs[c * 64 + u] = xb[(long)c * NS + u];
    }

    const int lane = tid & 31;
    const int wid  = tid >> 5;
    const int c0   = lane * 2;     // channel pair this thread owns
    const int t0   = wid * 8;      // 8 voxels this thread owns

    const float* Wsrc[3] = {Wq, Wk, Wv};
    const float* bsrc[3] = {bq, bk, bv};
    float* gout[3];
    gout[0] = g_q; gout[1] = g_k; gout[2] = g_v;

#pragma unroll
    for (int m = 0; m < 3; m++) {
        __syncthreads();  // previous iteration done reading WT/bs
        const float* W = Wsrc[m];
#pragma unroll
        for (int k2 = 0; k2 < 16; k2++) {
            int idx = tid + k2 * 256;
            int c = idx >> 6, j = idx & 63;
            WT[j * 66 + c] = W[idx];   // transpose, pitch 66 (conflict-free-ish)
        }
        if (tid < 64) bs[tid] = bsrc[m][tid];
        __syncthreads();

        float acc0[8], acc1[8];
        const float bias0 = bs[c0], bias1 = bs[c0 + 1];
#pragma unroll
        for (int v = 0; v < 8; v++) { acc0[v] = bias0; acc1[v] = bias1; }

#pragma unroll 4
        for (int j = 0; j < 64; j++) {
            float2 w  = *(const float2*)&WT[j * 66 + c0];
            float4 xa = *(const float4*)&Xs[j * 64 + t0];
            float4 xc = *(const float4*)&Xs[j * 64 + t0 + 4];
            float xv[8] = {xa.x, xa.y, xa.z, xa.w, xc.x, xc.y, xc.z, xc.w};
#pragma unroll
            for (int v = 0; v < 8; v++) {
                acc0[v] = fmaf(w.x, xv[v], acc0[v]);
                acc1[v] = fmaf(w.y, xv[v], acc1[v]);
            }
        }

        const float scale = (m == 0) ? 0.25f : 1.0f;  // hd^-0.5 = 16^-0.5
        float* g = gout[m];
#pragma unroll
        for (int v = 0; v < 8; v++) {
            int n = bb * NS + s0 + t0 + v;
            float2 o;
            o.x = acc0[v] * scale;
            o.y = acc1[v] * scale;
            *(float2*)&g[(long)n * NC + c0] = o;
        }
    }
}

// ---------------------------------------------------------------------------
// Kernel 2: 3x3x3 local attention + residual.
// One voxel per half-warp (16 lanes); lane owns 4 channels (float4).
// Quad (4 lanes) = one head (16 channels); 2-shfl reduction for q.k.
// Online softmax over 27 neighbors; zero-padded borders contribute
// logit 0 with zero v (matching jnp.pad semantics).
// Block = 256 threads = 8 warps = 16 consecutive voxels; smem transpose
// for coalesced channel-major output with residual add.
// ---------------------------------------------------------------------------
__global__ __launch_bounds__(256) void k_attn(
    const float* __restrict__ x, float* __restrict__ out)
{
    __shared__ float hs[64 * 17];

    const int tid  = threadIdx.x;
    const int lane = tid & 31;
    const int wid  = tid >> 5;

    const int n0 = blockIdx.x * 16;      // 16 voxels per block, 13824 % 16 == 0
    const int bb = n0 / NS;
    const int s0 = n0 % NS;

    const int half = lane >> 4;          // which voxel in this warp
    const int l4   = lane & 15;
    const int vloc = wid * 2 + half;     // voxel slot within block [0,16)
    const int s    = s0 + vloc;
    const int d = s / 576, h = (s / 24) % 24, w = s % 24;
    const int c0 = (l4 >> 2) * 16 + (l4 & 3) * 4;  // 4 channels of head l4>>2
    const int n  = bb * NS + s;

    const float4 q = *(const float4*)&g_q[(long)n * NC + c0];

    float m = -1e30f, lsum = 0.0f;
    float a0 = 0.f, a1 = 0.f, a2 = 0.f, a3 = 0.f;

#pragma unroll
    for (int di = -1; di <= 1; di++) {
#pragma unroll
        for (int hi = -1; hi <= 1; hi++) {
#pragma unroll
            for (int wi = -1; wi <= 1; wi++) {
                int zd = d + di, zh = h + hi, zw = w + wi;
                bool in = ((unsigned)zd < 24u) & ((unsigned)zh < 24u) & ((unsigned)zw < 24u);
                float sc;
                float4 vv;
                if (in) {
                    int nb = bb * NS + zd * 576 + zh * 24 + zw;
                    float4 kk = *(const float4*)&g_k[(long)nb * NC + c0];
                    vv        = *(const float4*)&g_v[(long)nb * NC + c0];
                    sc = q.x * kk.x + q.y * kk.y + q.z * kk.z + q.w * kk.w;
                } else {
                    sc = 0.0f;                       // dot with zero padding
                    vv = make_float4(0.f, 0.f, 0.f, 0.f);
                }
                // reduce over the quad (full 16-dim head dot product)
                sc += __shfl_xor_sync(0xffffffffu, sc, 1);
                sc += __shfl_xor_sync(0xffffffffu, sc, 2);

                float mn   = fmaxf(m, sc);
                float p    = __expf(sc - mn);
                float corr = __expf(m - mn);
                lsum = lsum * corr + p;
                a0 = fmaf(p, vv.x, a0 * corr);
                a1 = fmaf(p, vv.y, a1 * corr);
                a2 = fmaf(p, vv.z, a2 * corr);
                a3 = fmaf(p, vv.w, a3 * corr);
                m = mn;
            }
        }
    }

    const float inv = 1.0f / lsum;
    hs[(c0 + 0) * 17 + vloc] = a0 * inv;
    hs[(c0 + 1) * 17 + vloc] = a1 * inv;
    hs[(c0 + 2) * 17 + vloc] = a2 * inv;
    hs[(c0 + 3) * 17 + vloc] = a3 * inv;
    __syncthreads();

    // Coalesced channel-major output with residual add
#pragma unroll
    for (int k = 0; k < 4; k++) {
        int idx = tid + k * 256;
        int c = idx >> 4, t = idx & 15;
        long gi = ((long)bb * NC + c) * NS + s0 + t;
        out[gi] = hs[c * 17 + t] + x[gi];
    }
}

// ---------------------------------------------------------------------------
extern "C" void kernel_launch(void* const* d_in, const int* in_sizes, int n_in,
                              void* d_out, int out_size)
{
    const float* x  = (const float*)d_in[0];
    // d_in[1] = cemb (unused by reference forward)
    const float* Wq = (const float*)d_in[2];
    const float* bq = (const float*)d_in[3];
    const float* Wk = (const float*)d_in[4];
    const float* bk = (const float*)d_in[5];
    const float* Wv = (const float*)d_in[6];
    const float* bv = (const float*)d_in[7];
    float* out = (float*)d_out;

    k_proj<<<NVOX / 64, 256>>>(x, Wq, bq, Wk, bk, Wv, bv);
    k_attn<<<NVOX / 16, 256>>>(x, out);
}